// round 3
// baseline (speedup 1.0000x reference)
#include <cuda_runtime.h>
#include <math.h>

#define CD    2048
#define BB    2
#define LQ    4096
#define CTXT  512
#define IMGL  257
#define LCTX  769
#define NHEADS 16
#define HDIM  128

// ---------------- scratch (device globals; no allocation allowed) ----------------
__device__ float g_q [BB * LQ   * CD];   // 64 MB
__device__ float g_k [BB * CTXT * CD];   // 8 MB
__device__ float g_v [BB * CTXT * CD];   // 8 MB
__device__ float g_ki[BB * IMGL * CD];   // ~4.2 MB
__device__ float g_vi[BB * IMGL * CD];   // ~4.2 MB
__device__ float g_at[BB * LQ   * CD];   // 64 MB

// ---------------- packed fp32x2 helpers (sm_103a FFMA2) ----------------
__device__ __forceinline__ unsigned long long pack2(float x) {
    unsigned long long r;
    unsigned xi = __float_as_uint(x);
    asm("mov.b64 %0, {%1, %2};" : "=l"(r) : "r"(xi), "r"(xi));
    return r;
}
__device__ __forceinline__ void fma2(unsigned long long& c, unsigned long long a,
                                     unsigned long long b) {
    asm("fma.rn.f32x2 %0, %1, %2, %0;" : "+l"(c) : "l"(a), "l"(b));
}
__device__ __forceinline__ float2 unpack2(unsigned long long v) {
    unsigned lo, hi;
    asm("mov.b64 {%0, %1}, %2;" : "=r"(lo), "=r"(hi) : "l"(v));
    return make_float2(__uint_as_float(lo), __uint_as_float(hi));
}

// ---------------- GEMM + bias: Y[m][n] = sum_k A[src(m)][k] * W[k][n] + bias[n] ----
// src(m) = (m / rpb) * bstride + roff + (m % rpb)   (row gather for context slices)
// Tiles: BM=BN=128, BK=16; 256 threads; 8x8 outputs/thread via fp32x2 packed FMA.
__global__ __launch_bounds__(256, 2) void gemm_bias_kernel(
    const float* __restrict__ A, const float* __restrict__ W,
    const float* __restrict__ bias, float* __restrict__ Y,
    int R, int rpb, int bstride, int roff)
{
    __shared__ float As[16][132];   // transposed A tile: As[k][m]
    __shared__ float Ws[16][128];   // Ws[k][n]
    const int tx = threadIdx.x & 15;
    const int ty = threadIdx.x >> 4;
    const int row0 = blockIdx.y * 128;
    const int col0 = blockIdx.x * 128;

    unsigned long long c2[8][4];
#pragma unroll
    for (int i = 0; i < 8; i++)
#pragma unroll
        for (int j = 0; j < 4; j++) c2[i][j] = 0ull;

    for (int kt = 0; kt < CD; kt += 16) {
        // load A tile (transposed into smem)
#pragma unroll
        for (int it = 0; it < 2; it++) {
            int f  = threadIdx.x + it * 256;   // float4 index within 128x16 tile
            int ml = f >> 2, kq = f & 3;
            int m  = row0 + ml;
            float4 av = make_float4(0.f, 0.f, 0.f, 0.f);
            if (m < R) {
                size_t src = (size_t)((m / rpb) * bstride + roff + (m % rpb));
                av = *reinterpret_cast<const float4*>(A + src * CD + kt + kq * 4);
            }
            As[kq * 4 + 0][ml] = av.x;
            As[kq * 4 + 1][ml] = av.y;
            As[kq * 4 + 2][ml] = av.z;
            As[kq * 4 + 3][ml] = av.w;
        }
        // load W tile
#pragma unroll
        for (int it = 0; it < 2; it++) {
            int f  = threadIdx.x + it * 256;
            int kl = f >> 5, nq = f & 31;
            *reinterpret_cast<float4*>(&Ws[kl][nq * 4]) =
                *reinterpret_cast<const float4*>(W + (size_t)(kt + kl) * CD + col0 + nq * 4);
        }
        __syncthreads();

#pragma unroll
        for (int kk = 0; kk < 16; kk++) {
            float4 a0 = *reinterpret_cast<const float4*>(&As[kk][ty * 8]);
            float4 a1 = *reinterpret_cast<const float4*>(&As[kk][ty * 8 + 4]);
            unsigned long long bb[4];
#pragma unroll
            for (int j = 0; j < 4; j++)
                bb[j] = *reinterpret_cast<const unsigned long long*>(&Ws[kk][tx * 8 + j * 2]);
            float a_[8] = {a0.x, a0.y, a0.z, a0.w, a1.x, a1.y, a1.z, a1.w};
#pragma unroll
            for (int i = 0; i < 8; i++) {
                unsigned long long ad = pack2(a_[i]);
#pragma unroll
                for (int j = 0; j < 4; j++) fma2(c2[i][j], ad, bb[j]);
            }
        }
        __syncthreads();
    }

#pragma unroll
    for (int i = 0; i < 8; i++) {
        int m = row0 + ty * 8 + i;
        if (m >= R) continue;
#pragma unroll
        for (int j = 0; j < 4; j++) {
            int n = col0 + tx * 8 + j * 2;
            float2 v  = unpack2(c2[i][j]);
            float2 bv = *reinterpret_cast<const float2*>(bias + n);
            v.x += bv.x;
            v.y += bv.y;
            *reinterpret_cast<float2*>(Y + (size_t)m * CD + n) = v;
        }
    }
}

// ---------------- RMSNorm over last dim (2048), in place, with gain g -------------
__global__ void rmsnorm_kernel(float* __restrict__ Y, const float* __restrict__ g)
{
    const int row = blockIdx.x;
    float* y = Y + (size_t)row * CD;
    float4 v0 = reinterpret_cast<float4*>(y)[threadIdx.x];
    float4 v1 = reinterpret_cast<float4*>(y)[threadIdx.x + 256];
    float ss = v0.x * v0.x + v0.y * v0.y + v0.z * v0.z + v0.w * v0.w
             + v1.x * v1.x + v1.y * v1.y + v1.z * v1.z + v1.w * v1.w;
#pragma unroll
    for (int o = 16; o > 0; o >>= 1) ss += __shfl_xor_sync(0xffffffffu, ss, o);
    __shared__ float red[8];
    if ((threadIdx.x & 31) == 0) red[threadIdx.x >> 5] = ss;
    __syncthreads();
    float tot = 0.f;
#pragma unroll
    for (int i = 0; i < 8; i++) tot += red[i];
    float s = rsqrtf(tot * (1.0f / 2048.0f) + 1e-6f);
    float4 g0 = reinterpret_cast<const float4*>(g)[threadIdx.x];
    float4 g1 = reinterpret_cast<const float4*>(g)[threadIdx.x + 256];
    v0.x *= s * g0.x; v0.y *= s * g0.y; v0.z *= s * g0.z; v0.w *= s * g0.w;
    v1.x *= s * g1.x; v1.y *= s * g1.y; v1.z *= s * g1.z; v1.w *= s * g1.w;
    reinterpret_cast<float4*>(y)[threadIdx.x]       = v0;
    reinterpret_cast<float4*>(y)[threadIdx.x + 256] = v1;
}

// ---------------- Dual-softmax flash attention (fp32 SIMT) ------------------------
// Block = one (b, h, 64-query tile). Phase 0: 257 img keys. Phase 1: masked txt keys.
// Each phase has its own online softmax; results are normalized per-phase and summed.
__global__ __launch_bounds__(256, 1) void attn_kernel(const int* __restrict__ lens)
{
    extern __shared__ float sm[];
    float* Qs   = sm;                    // 64 x 132
    float* Kst  = Qs  + 64 * 132;        // transposed: 128 x 68  (Kst[d][k])
    float* Vs   = Kst + 128 * 68;        // 64 x 128
    float* S    = Vs  + 64 * 128;        // 64 x 65
    float* rowm = S + 64 * 65;
    float* rowl = rowm + 64;
    float* rowr = rowl + 64;

    const int tid = threadIdx.x;
    const int tx  = tid & 15;
    const int ty  = tid >> 4;
    const int qt = blockIdx.x, h = blockIdx.y, b = blockIdx.z;
    const int q0 = qt * 64;
    const float scale = 0.08838834764831845f;   // 1/sqrt(128)
    const float NEG_INF = __int_as_float(0xff800000u);

    // load Q tile
    const float* qbase = g_q + ((size_t)(b * LQ + q0)) * CD + h * HDIM;
#pragma unroll
    for (int it = 0; it < 8; it++) {
        int f = tid + it * 256;
        int r = f >> 5, dq = f & 31;
        *reinterpret_cast<float4*>(&Qs[r * 132 + dq * 4]) =
            *reinterpret_cast<const float4*>(qbase + (size_t)r * CD + dq * 4);
    }

    float stash[4][8];
#pragma unroll
    for (int i = 0; i < 4; i++)
#pragma unroll
        for (int d = 0; d < 8; d++) stash[i][d] = 0.f;

    for (int phase = 0; phase < 2; phase++) {
        const float *Kb, *Vb;
        int nk;
        if (phase == 0) {
            Kb = g_ki + (size_t)b * IMGL * CD + h * HDIM;
            Vb = g_vi + (size_t)b * IMGL * CD + h * HDIM;
            nk = IMGL;
        } else {
            Kb = g_k + (size_t)b * CTXT * CD + h * HDIM;
            Vb = g_v + (size_t)b * CTXT * CD + h * HDIM;
            nk = lens[b];
            nk = nk < 1 ? 1 : (nk > CTXT ? CTXT : nk);
        }
        float acc[4][8];
#pragma unroll
        for (int i = 0; i < 4; i++)
#pragma unroll
            for (int d = 0; d < 8; d++) acc[i][d] = 0.f;

        __syncthreads();   // previous phase done reading rowl before reset
        if (tid < 64) { rowm[tid] = NEG_INF; rowl[tid] = 0.f; }

        for (int j0 = 0; j0 < nk; j0 += 64) {
            // K tile: transpose-load into Kst[d][k] (conflict-free QK^T b-operand)
#pragma unroll
            for (int it = 0; it < 8; it++) {
                int f   = tid + it * 256;
                int dql = f & 3;
                int r   = (f >> 2) & 63;
                int dq  = (f >> 8) * 4 + dql;
                float4 kv = make_float4(0.f, 0.f, 0.f, 0.f);
                if (j0 + r < nk)
                    kv = *reinterpret_cast<const float4*>(Kb + (size_t)(j0 + r) * CD + dq * 4);
                Kst[(dq * 4 + 0) * 68 + r] = kv.x;
                Kst[(dq * 4 + 1) * 68 + r] = kv.y;
                Kst[(dq * 4 + 2) * 68 + r] = kv.z;
                Kst[(dq * 4 + 3) * 68 + r] = kv.w;
            }
            // V tile (zero-filled beyond nk: keeps 0*garbage NaNs out of PV)
#pragma unroll
            for (int it = 0; it < 8; it++) {
                int f = tid + it * 256;
                int r = f >> 5, dq = f & 31;
                float4 vv = make_float4(0.f, 0.f, 0.f, 0.f);
                if (j0 + r < nk)
                    vv = *reinterpret_cast<const float4*>(Vb + (size_t)(j0 + r) * CD + dq * 4);
                *reinterpret_cast<float4*>(&Vs[r * 128 + dq * 4]) = vv;
            }
            __syncthreads();

            // S = Q K^T  (each thread: 4 q-rows x 4 k-cols)
            float sc[4][4];
#pragma unroll
            for (int i = 0; i < 4; i++)
#pragma unroll
                for (int j = 0; j < 4; j++) sc[i][j] = 0.f;
#pragma unroll 4
            for (int d = 0; d < 128; d++) {
                float4 bb = *reinterpret_cast<const float4*>(&Kst[d * 68 + tx * 4]);
#pragma unroll
                for (int i = 0; i < 4; i++) {
                    float a = Qs[(ty * 4 + i) * 132 + d];
                    sc[i][0] += a * bb.x;
                    sc[i][1] += a * bb.y;
                    sc[i][2] += a * bb.z;
                    sc[i][3] += a * bb.w;
                }
            }
#pragma unroll
            for (int i = 0; i < 4; i++)
#pragma unroll
                for (int j = 0; j < 4; j++) {
                    int kidx = j0 + tx * 4 + j;
                    S[(ty * 4 + i) * 65 + tx * 4 + j] =
                        (kidx < nk) ? sc[i][j] * scale : -1e30f;
                }
            __syncthreads();

            // online softmax update (one thread per query row)
            if (tid < 64) {
                float mo = rowm[tid];
                float mx = mo;
#pragma unroll 8
                for (int j = 0; j < 64; j++) mx = fmaxf(mx, S[tid * 65 + j]);
                float rr = __expf(mo - mx);     // mo=-inf -> 0
                float sum = 0.f;
#pragma unroll 8
                for (int j = 0; j < 64; j++) {
                    float p = __expf(S[tid * 65 + j] - mx);
                    S[tid * 65 + j] = p;
                    sum += p;
                }
                rowl[tid] = rowl[tid] * rr + sum;
                rowm[tid] = mx;
                rowr[tid] = rr;
            }
            __syncthreads();

            // O = O*r + P V   (each thread: 4 q-rows x 8 dims)
            float rs[4];
#pragma unroll
            for (int i = 0; i < 4; i++) rs[i] = rowr[ty * 4 + i];
#pragma unroll
            for (int i = 0; i < 4; i++)
#pragma unroll
                for (int d = 0; d < 8; d++) acc[i][d] *= rs[i];
#pragma unroll 2
            for (int kk = 0; kk < 64; kk++) {
                float4 v0 = *reinterpret_cast<const float4*>(&Vs[kk * 128 + tx * 8]);
                float4 v1 = *reinterpret_cast<const float4*>(&Vs[kk * 128 + tx * 8 + 4]);
#pragma unroll
                for (int i = 0; i < 4; i++) {
                    float p = S[(ty * 4 + i) * 65 + kk];
                    acc[i][0] += p * v0.x; acc[i][1] += p * v0.y;
                    acc[i][2] += p * v0.z; acc[i][3] += p * v0.w;
                    acc[i][4] += p * v1.x; acc[i][5] += p * v1.y;
                    acc[i][6] += p * v1.z; acc[i][7] += p * v1.w;
                }
            }
            __syncthreads();
        }

        // per-phase normalization, accumulate into stash
#pragma unroll
        for (int i = 0; i < 4; i++) {
            float li = 1.f / rowl[ty * 4 + i];
#pragma unroll
            for (int d = 0; d < 8; d++) stash[i][d] += acc[i][d] * li;
        }
    }

    // write attention output
    float* obase = g_at + ((size_t)(b * LQ + q0)) * CD + h * HDIM;
#pragma unroll
    for (int i = 0; i < 4; i++) {
        float4 o0 = make_float4(stash[i][0], stash[i][1], stash[i][2], stash[i][3]);
        float4 o1 = make_float4(stash[i][4], stash[i][5], stash[i][6], stash[i][7]);
        *reinterpret_cast<float4*>(obase + (size_t)(ty * 4 + i) * CD + tx * 8)     = o0;
        *reinterpret_cast<float4*>(obase + (size_t)(ty * 4 + i) * CD + tx * 8 + 4) = o1;
    }
}

// --------------------------------- launch ----------------------------------------
extern "C" void kernel_launch(void* const* d_in, const int* in_sizes, int n_in,
                              void* d_out, int out_size)
{
    const float* x    = (const float*)d_in[0];
    const float* ctx  = (const float*)d_in[1];
    const int*   lens = (const int*)  d_in[2];
    const float* Wq  = (const float*)d_in[3];
    const float* bq  = (const float*)d_in[4];
    const float* gq  = (const float*)d_in[5];
    const float* Wk  = (const float*)d_in[6];
    const float* bk  = (const float*)d_in[7];
    const float* gk  = (const float*)d_in[8];
    const float* Wv  = (const float*)d_in[9];
    const float* bv  = (const float*)d_in[10];
    const float* Wki = (const float*)d_in[11];
    const float* bki = (const float*)d_in[12];
    const float* gki = (const float*)d_in[13];
    const float* Wvi = (const float*)d_in[14];
    const float* bvi = (const float*)d_in[15];
    const float* Wo  = (const float*)d_in[16];
    const float* bo  = (const float*)d_in[17];
    float* out = (float*)d_out;

    float *q, *k, *v, *ki, *vi, *at;
    cudaGetSymbolAddress((void**)&q,  g_q);
    cudaGetSymbolAddress((void**)&k,  g_k);
    cudaGetSymbolAddress((void**)&v,  g_v);
    cudaGetSymbolAddress((void**)&ki, g_ki);
    cudaGetSymbolAddress((void**)&vi, g_vi);
    cudaGetSymbolAddress((void**)&at, g_at);

    dim3 blk(256);

    // projections (+ RMSNorm where the reference applies it)
    gemm_bias_kernel<<<dim3(16, 64), blk>>>(x,   Wq,  bq,  q,  BB * LQ,   LQ,   LQ,   0);
    rmsnorm_kernel<<<BB * LQ, 256>>>(q, gq);

    gemm_bias_kernel<<<dim3(16, 8),  blk>>>(ctx, Wk,  bk,  k,  BB * CTXT, CTXT, LCTX, IMGL);
    rmsnorm_kernel<<<BB * CTXT, 256>>>(k, gk);

    gemm_bias_kernel<<<dim3(16, 8),  blk>>>(ctx, Wv,  bv,  v,  BB * CTXT, CTXT, LCTX, IMGL);

    gemm_bias_kernel<<<dim3(16, 5),  blk>>>(ctx, Wki, bki, ki, BB * IMGL, IMGL, LCTX, 0);
    rmsnorm_kernel<<<BB * IMGL, 256>>>(ki, gki);

    gemm_bias_kernel<<<dim3(16, 5),  blk>>>(ctx, Wvi, bvi, vi, BB * IMGL, IMGL, LCTX, 0);

    // dual-softmax attention
    const int attn_smem = (64 * 132 + 128 * 68 + 64 * 128 + 64 * 65 + 3 * 64) * 4;
    cudaFuncSetAttribute(attn_kernel, cudaFuncAttributeMaxDynamicSharedMemorySize, attn_smem);
    attn_kernel<<<dim3(64, NHEADS, BB), 256, attn_smem>>>(lens);

    // output projection -> d_out
    gemm_bias_kernel<<<dim3(16, 64), blk>>>(at, Wo, bo, out, BB * LQ, LQ, LQ, 0);
}

// round 5
// speedup vs baseline: 1.5143x; 1.5143x over previous
#include <cuda_runtime.h>
#include <cuda_bf16.h>
#include <cstdint>
#include <math.h>

#define CD    2048
#define BB    2
#define LQ    4096
#define CTXT  512
#define IMGL  257
#define IMGP  384          // padded img rows per batch (3 x 128)
#define LCTX  769
#define NHEADS 16
#define HDIM  128

// ---------------- scratch (device globals; no allocation allowed) ----------------
__device__ float g_q [BB * LQ   * CD];
__device__ float g_k [BB * CTXT * CD];
__device__ float g_v [BB * CTXT * CD];
__device__ float g_ki[BB * IMGP * CD];
__device__ float g_vi[BB * IMGP * CD];
__device__ float g_at[BB * LQ   * CD];
__device__ __nv_bfloat16 g_xh[BB * LQ   * CD];
__device__ __nv_bfloat16 g_xl[BB * LQ   * CD];
__device__ __nv_bfloat16 g_ch[BB * LCTX * CD];
__device__ __nv_bfloat16 g_cl[BB * LCTX * CD];
__device__ __nv_bfloat16 g_wh[6 * CD * CD];
__device__ __nv_bfloat16 g_wl[6 * CD * CD];
__device__ __nv_bfloat16 g_ah[BB * LQ   * CD];
__device__ __nv_bfloat16 g_al[BB * LQ   * CD];

// ---------------- helpers ----------------
__device__ __forceinline__ uint32_t smem_u32(const void* p) {
    uint32_t a;
    asm("{ .reg .u64 t; cvta.to.shared.u64 t, %1; cvt.u32.u64 %0, t; }" : "=r"(a) : "l"(p));
    return a;
}
__device__ __forceinline__ void cp16(uint32_t dst, const void* src, uint32_t sz) {
    asm volatile("cp.async.cg.shared.global [%0], [%1], 16, %2;"
                 :: "r"(dst), "l"(src), "r"(sz) : "memory");
}
__device__ __forceinline__ void cp_commit() {
    asm volatile("cp.async.commit_group;" ::: "memory");
}
__device__ __forceinline__ void ldsm4(uint32_t* r, uint32_t addr) {
    asm volatile("ldmatrix.sync.aligned.m8n8.x4.shared.b16 {%0,%1,%2,%3}, [%4];"
                 : "=r"(r[0]), "=r"(r[1]), "=r"(r[2]), "=r"(r[3]) : "r"(addr));
}
__device__ __forceinline__ void mma16816(float* c, const uint32_t* a, const uint32_t* b) {
    asm volatile(
        "mma.sync.aligned.m16n8k16.row.col.f32.bf16.bf16.f32 "
        "{%0,%1,%2,%3}, {%4,%5,%6,%7}, {%8,%9}, {%0,%1,%2,%3};"
        : "+f"(c[0]), "+f"(c[1]), "+f"(c[2]), "+f"(c[3])
        : "r"(a[0]), "r"(a[1]), "r"(a[2]), "r"(a[3]), "r"(b[0]), "r"(b[1]));
}

// ---------------- conversion kernels ----------------
__global__ void conv_hilo(const float* __restrict__ in, __nv_bfloat16* __restrict__ hi,
                          __nv_bfloat16* __restrict__ lo, int n)
{
    for (int i = blockIdx.x * blockDim.x + threadIdx.x; i < n; i += gridDim.x * blockDim.x) {
        float v = in[i];
        __nv_bfloat16 h = __float2bfloat16(v);
        hi[i] = h;
        lo[i] = __float2bfloat16(v - __bfloat162float(h));
    }
}

// W [K=2048][N=2048] fp32 -> Wt hi/lo [N][K] bf16
__global__ void wtrans(const float* __restrict__ W, __nv_bfloat16* __restrict__ th,
                       __nv_bfloat16* __restrict__ tl)
{
    __shared__ float t[32][33];
    const int x0 = blockIdx.x * 32;   // n
    const int y0 = blockIdx.y * 32;   // k
    const int tx = threadIdx.x, ty = threadIdx.y;
#pragma unroll
    for (int i = 0; i < 4; i++)
        t[ty + i * 8][tx] = W[(size_t)(y0 + ty + i * 8) * CD + x0 + tx];
    __syncthreads();
#pragma unroll
    for (int i = 0; i < 4; i++) {
        float v = t[tx][ty + i * 8];
        __nv_bfloat16 h = __float2bfloat16(v);
        size_t o = (size_t)(x0 + ty + i * 8) * CD + y0 + tx;
        th[o] = h;
        tl[o] = __float2bfloat16(v - __bfloat162float(h));
    }
}

// ---------------- split-bf16 GEMM via mma.sync (HMMA) -----------------------------
// Y[m][n] = sum_k A[src(m)][k] * Wt[n][k] + bias[n]
// CTA tile 128x128, BK=32, 8 warps (warp tile 32m x 64n), cp.async double buffer.
// Smem layout: 8x8-bf16 tiles, each tile = one contiguous 128B line:
//   addr(r, k) = (ktile*16 + rtile)*128 + (r&7)*16 + (k&7)*2,  ktile=k>>3, rtile=r>>3
#define OFF_AH 0
#define OFF_AL 8192
#define OFF_BH 16384
#define OFF_BL 24576
#define STAGE  32768
#define NCHUNK 64

__global__ __launch_bounds__(256, 2)
void mm_gemm(const __nv_bfloat16* __restrict__ Ahg, const __nv_bfloat16* __restrict__ Alg,
             const __nv_bfloat16* __restrict__ Bhg, const __nv_bfloat16* __restrict__ Blg,
             const float* __restrict__ bias, float* __restrict__ Y,
             int rpb, int rvalid, int bstride, int roff)
{
    extern __shared__ char smem[];
    const uint32_t sb = smem_u32(smem);
    const int tid  = threadIdx.x;
    const int lane = tid & 31;
    const int wid  = tid >> 5;
    const int wm = wid & 3, wn = wid >> 2;
    const int m0w = wm * 32, n0w = wn * 64;
    const int row0 = blockIdx.y * 128;
    const int col0 = blockIdx.x * 128;

    // per-thread load geometry (constant across chunks)
    const int lm   = tid & 127;            // smem row (both A-m and B-n loads)
    const int kq0  = (tid >> 7) * 2;       // first of two 16B k-chunks
    const int mg   = row0 + lm;
    const int qb   = mg / rpb;
    const int rr   = mg - qb * rpb;
    const uint32_t aSz = (rr < rvalid) ? 16u : 0u;
    const size_t aRow = ((size_t)(qb * bstride + roff + rr)) * CD;
    const size_t bRow = ((size_t)(col0 + lm)) * CD;
    const uint32_t sRow = (uint32_t)((lm >> 3) * 128 + (lm & 7) * 16);

    auto issue = [&](int c, int st) {
        const uint32_t base = sb + st * STAGE;
        const int gk = c * 32;
#pragma unroll
        for (int i = 0; i < 2; i++) {
            const int kq = kq0 + i;
            const uint32_t so = (uint32_t)(kq * 2048) + sRow;
            const size_t go = gk + kq * 8;
            cp16(base + OFF_AH + so, Ahg + aRow + go, aSz);
            cp16(base + OFF_AL + so, Alg + aRow + go, aSz);
            cp16(base + OFF_BH + so, Bhg + bRow + go, 16u);
            cp16(base + OFF_BL + so, Blg + bRow + go, 16u);
        }
    };

    float acc[2][8][4];
#pragma unroll
    for (int i = 0; i < 2; i++)
#pragma unroll
        for (int j = 0; j < 8; j++)
#pragma unroll
            for (int q = 0; q < 4; q++) acc[i][j][q] = 0.f;

    // per-lane ldmatrix constant address parts
    uint32_t cpa[2], cpb[4];
#pragma unroll
    for (int mt = 0; mt < 2; mt++) {
        int ml = m0w + mt * 16 + ((lane >> 3) & 1) * 8 + (lane & 7);
        cpa[mt] = (uint32_t)((ml >> 3) * 128 + (ml & 7) * 16);
    }
#pragma unroll
    for (int p = 0; p < 4; p++) {
        int nl = n0w + p * 16 + (lane >> 4) * 8 + (lane & 7);
        cpb[p] = (uint32_t)((nl >> 3) * 128 + (nl & 7) * 16);
    }
    const uint32_t ktA = (uint32_t)(lane >> 4);        // A: +ktile from lane
    const uint32_t ktB = (uint32_t)((lane >> 3) & 1);  // B: +ktile from lane

    issue(0, 0); cp_commit();
    issue(1, 1); cp_commit();

    for (int c = 0; c < NCHUNK; c++) {
        if (c + 1 < NCHUNK) asm volatile("cp.async.wait_group 1;" ::: "memory");
        else                asm volatile("cp.async.wait_group 0;" ::: "memory");
        __syncthreads();

        const uint32_t base = sb + (c & 1) * STAGE;
#pragma unroll
        for (int ks = 0; ks < 2; ks++) {
            const uint32_t ktb = (uint32_t)(ks * 2);
            uint32_t aH[2][4], aL[2][4], b[8][2];
#pragma unroll
            for (int mt = 0; mt < 2; mt++) {
                uint32_t ao = (ktb + ktA) * 2048 + cpa[mt];
                ldsm4(aH[mt], base + OFF_AH + ao);
                ldsm4(aL[mt], base + OFF_AL + ao);
            }
#pragma unroll
            for (int p = 0; p < 4; p++) {
                uint32_t bo = (ktb + ktB) * 2048 + cpb[p];
                ldsm4(&b[2 * p][0], base + OFF_BH + bo);
            }
#pragma unroll
            for (int mt = 0; mt < 2; mt++)
#pragma unroll
                for (int nt = 0; nt < 8; nt++) mma16816(acc[mt][nt], aH[mt], b[nt]);
#pragma unroll
            for (int mt = 0; mt < 2; mt++)
#pragma unroll
                for (int nt = 0; nt < 8; nt++) mma16816(acc[mt][nt], aL[mt], b[nt]);
#pragma unroll
            for (int p = 0; p < 4; p++) {
                uint32_t bo = (ktb + ktB) * 2048 + cpb[p];
                ldsm4(&b[2 * p][0], base + OFF_BL + bo);
            }
#pragma unroll
            for (int mt = 0; mt < 2; mt++)
#pragma unroll
                for (int nt = 0; nt < 8; nt++) mma16816(acc[mt][nt], aH[mt], b[nt]);
        }
        __syncthreads();
        if (c + 2 < NCHUNK) { issue(c + 2, c & 1); cp_commit(); }
    }

    // epilogue: direct stores + bias
#pragma unroll
    for (int mt = 0; mt < 2; mt++) {
        const int rbase = row0 + m0w + mt * 16 + (lane >> 2);
#pragma unroll
        for (int nt = 0; nt < 8; nt++) {
            const int col = col0 + n0w + nt * 8 + (lane & 3) * 2;
            const float2 bv = *reinterpret_cast<const float2*>(bias + col);
            float2 v0 = make_float2(acc[mt][nt][0] + bv.x, acc[mt][nt][1] + bv.y);
            float2 v1 = make_float2(acc[mt][nt][2] + bv.x, acc[mt][nt][3] + bv.y);
            *reinterpret_cast<float2*>(Y + (size_t)rbase * CD + col)       = v0;
            *reinterpret_cast<float2*>(Y + (size_t)(rbase + 8) * CD + col) = v1;
        }
    }
}

// ---------------- RMSNorm over last dim (2048), in place, with gain g -------------
__global__ void rmsnorm_kernel(float* __restrict__ Y, const float* __restrict__ g)
{
    const int row = blockIdx.x;
    float* y = Y + (size_t)row * CD;
    float4 v0 = reinterpret_cast<float4*>(y)[threadIdx.x];
    float4 v1 = reinterpret_cast<float4*>(y)[threadIdx.x + 256];
    float ss = v0.x * v0.x + v0.y * v0.y + v0.z * v0.z + v0.w * v0.w
             + v1.x * v1.x + v1.y * v1.y + v1.z * v1.z + v1.w * v1.w;
#pragma unroll
    for (int o = 16; o > 0; o >>= 1) ss += __shfl_xor_sync(0xffffffffu, ss, o);
    __shared__ float red[8];
    if ((threadIdx.x & 31) == 0) red[threadIdx.x >> 5] = ss;
    __syncthreads();
    float tot = 0.f;
#pragma unroll
    for (int i = 0; i < 8; i++) tot += red[i];
    float s = rsqrtf(tot * (1.0f / 2048.0f) + 1e-6f);
    float4 g0 = reinterpret_cast<const float4*>(g)[threadIdx.x];
    float4 g1 = reinterpret_cast<const float4*>(g)[threadIdx.x + 256];
    v0.x *= s * g0.x; v0.y *= s * g0.y; v0.z *= s * g0.z; v0.w *= s * g0.w;
    v1.x *= s * g1.x; v1.y *= s * g1.y; v1.z *= s * g1.z; v1.w *= s * g1.w;
    reinterpret_cast<float4*>(y)[threadIdx.x]       = v0;
    reinterpret_cast<float4*>(y)[threadIdx.x + 256] = v1;
}

// ---------------- Dual-softmax flash attention (fp32 SIMT) ------------------------
__global__ __launch_bounds__(256, 1) void attn_kernel(const int* __restrict__ lens)
{
    extern __shared__ float sm[];
    float* Qs   = sm;                    // 64 x 132
    float* Kst  = Qs  + 64 * 132;        // transposed: 128 x 68  (Kst[d][k])
    float* Vs   = Kst + 128 * 68;        // 64 x 128
    float* S    = Vs  + 64 * 128;        // 64 x 65
    float* rowm = S + 64 * 65;
    float* rowl = rowm + 64;
    float* rowr = rowl + 64;

    const int tid = threadIdx.x;
    const int tx  = tid & 15;
    const int ty  = tid >> 4;
    const int qt = blockIdx.x, h = blockIdx.y, b = blockIdx.z;
    const int q0 = qt * 64;
    const float scale = 0.08838834764831845f;
    const float NEG_INF = __int_as_float(0xff800000u);

    const float* qbase = g_q + ((size_t)(b * LQ + q0)) * CD + h * HDIM;
#pragma unroll
    for (int it = 0; it < 8; it++) {
        int f = tid + it * 256;
        int r = f >> 5, dq = f & 31;
        *reinterpret_cast<float4*>(&Qs[r * 132 + dq * 4]) =
            *reinterpret_cast<const float4*>(qbase + (size_t)r * CD + dq * 4);
    }

    float stash[4][8];
#pragma unroll
    for (int i = 0; i < 4; i++)
#pragma unroll
        for (int d = 0; d < 8; d++) stash[i][d] = 0.f;

    for (int phase = 0; phase < 2; phase++) {
        const float *Kb, *Vb;
        int nk;
        if (phase == 0) {
            Kb = g_ki + (size_t)b * IMGP * CD + h * HDIM;
            Vb = g_vi + (size_t)b * IMGP * CD + h * HDIM;
            nk = IMGL;
        } else {
            Kb = g_k + (size_t)b * CTXT * CD + h * HDIM;
            Vb = g_v + (size_t)b * CTXT * CD + h * HDIM;
            nk = lens[b];
            nk = nk < 1 ? 1 : (nk > CTXT ? CTXT : nk);
        }
        float acc[4][8];
#pragma unroll
        for (int i = 0; i < 4; i++)
#pragma unroll
            for (int d = 0; d < 8; d++) acc[i][d] = 0.f;

        __syncthreads();
        if (tid < 64) { rowm[tid] = NEG_INF; rowl[tid] = 0.f; }

        for (int j0 = 0; j0 < nk; j0 += 64) {
#pragma unroll
            for (int it = 0; it < 8; it++) {
                int f   = tid + it * 256;
                int dql = f & 3;
                int r   = (f >> 2) & 63;
                int dq  = (f >> 8) * 4 + dql;
                float4 kv = make_float4(0.f, 0.f, 0.f, 0.f);
                if (j0 + r < nk)
                    kv = *reinterpret_cast<const float4*>(Kb + (size_t)(j0 + r) * CD + dq * 4);
                Kst[(dq * 4 + 0) * 68 + r] = kv.x;
                Kst[(dq * 4 + 1) * 68 + r] = kv.y;
                Kst[(dq * 4 + 2) * 68 + r] = kv.z;
                Kst[(dq * 4 + 3) * 68 + r] = kv.w;
            }
#pragma unroll
            for (int it = 0; it < 8; it++) {
                int f = tid + it * 256;
                int r = f >> 5, dq = f & 31;
                float4 vv = make_float4(0.f, 0.f, 0.f, 0.f);
                if (j0 + r < nk)
                    vv = *reinterpret_cast<const float4*>(Vb + (size_t)(j0 + r) * CD + dq * 4);
                *reinterpret_cast<float4*>(&Vs[r * 128 + dq * 4]) = vv;
            }
            __syncthreads();

            float sc[4][4];
#pragma unroll
            for (int i = 0; i < 4; i++)
#pragma unroll
                for (int j = 0; j < 4; j++) sc[i][j] = 0.f;
#pragma unroll 4
            for (int d = 0; d < 128; d++) {
                float4 bb = *reinterpret_cast<const float4*>(&Kst[d * 68 + tx * 4]);
#pragma unroll
                for (int i = 0; i < 4; i++) {
                    float a = Qs[(ty * 4 + i) * 132 + d];
                    sc[i][0] += a * bb.x;
                    sc[i][1] += a * bb.y;
                    sc[i][2] += a * bb.z;
                    sc[i][3] += a * bb.w;
                }
            }
#pragma unroll
            for (int i = 0; i < 4; i++)
#pragma unroll
                for (int j = 0; j < 4; j++) {
                    int kidx = j0 + tx * 4 + j;
                    S[(ty * 4 + i) * 65 + tx * 4 + j] =
                        (kidx < nk) ? sc[i][j] * scale : -1e30f;
                }
            __syncthreads();

            if (tid < 64) {
                float mo = rowm[tid];
                float mx = mo;
#pragma unroll 8
                for (int j = 0; j < 64; j++) mx = fmaxf(mx, S[tid * 65 + j]);
                float rr = __expf(mo - mx);
                float sum = 0.f;
#pragma unroll 8
                for (int j = 0; j < 64; j++) {
                    float p = __expf(S[tid * 65 + j] - mx);
                    S[tid * 65 + j] = p;
                    sum += p;
                }
                rowl[tid] = rowl[tid] * rr + sum;
                rowm[tid] = mx;
                rowr[tid] = rr;
            }
            __syncthreads();

            float rs[4];
#pragma unroll
            for (int i = 0; i < 4; i++) rs[i] = rowr[ty * 4 + i];
#pragma unroll
            for (int i = 0; i < 4; i++)
#pragma unroll
                for (int d = 0; d < 8; d++) acc[i][d] *= rs[i];
#pragma unroll 2
            for (int kk = 0; kk < 64; kk++) {
                float4 v0 = *reinterpret_cast<const float4*>(&Vs[kk * 128 + tx * 8]);
                float4 v1 = *reinterpret_cast<const float4*>(&Vs[kk * 128 + tx * 8 + 4]);
#pragma unroll
                for (int i = 0; i < 4; i++) {
                    float p = S[(ty * 4 + i) * 65 + kk];
                    acc[i][0] += p * v0.x; acc[i][1] += p * v0.y;
                    acc[i][2] += p * v0.z; acc[i][3] += p * v0.w;
                    acc[i][4] += p * v1.x; acc[i][5] += p * v1.y;
                    acc[i][6] += p * v1.z; acc[i][7] += p * v1.w;
                }
            }
            __syncthreads();
        }

#pragma unroll
        for (int i = 0; i < 4; i++) {
            float li = 1.f / rowl[ty * 4 + i];
#pragma unroll
            for (int d = 0; d < 8; d++) stash[i][d] += acc[i][d] * li;
        }
    }

    float* obase = g_at + ((size_t)(b * LQ + q0)) * CD + h * HDIM;
#pragma unroll
    for (int i = 0; i < 4; i++) {
        float4 o0 = make_float4(stash[i][0], stash[i][1], stash[i][2], stash[i][3]);
        float4 o1 = make_float4(stash[i][4], stash[i][5], stash[i][6], stash[i][7]);
        *reinterpret_cast<float4*>(obase + (size_t)(ty * 4 + i) * CD + tx * 8)     = o0;
        *reinterpret_cast<float4*>(obase + (size_t)(ty * 4 + i) * CD + tx * 8 + 4) = o1;
    }
}

// --------------------------------- launch ----------------------------------------
extern "C" void kernel_launch(void* const* d_in, const int* in_sizes, int n_in,
                              void* d_out, int out_size)
{
    const float* x    = (const float*)d_in[0];
    const float* ctx  = (const float*)d_in[1];
    const int*   lens = (const int*)  d_in[2];
    const float* Wq  = (const float*)d_in[3];
    const float* bq  = (const float*)d_in[4];
    const float* gq  = (const float*)d_in[5];
    const float* Wk  = (const float*)d_in[6];
    const float* bk  = (const float*)d_in[7];
    const float* gk  = (const float*)d_in[8];
    const float* Wv  = (const float*)d_in[9];
    const float* bv  = (const float*)d_in[10];
    const float* Wki = (const float*)d_in[11];
    const float* bki = (const float*)d_in[12];
    const float* gki = (const float*)d_in[13];
    const float* Wvi = (const float*)d_in[14];
    const float* bvi = (const float*)d_in[15];
    const float* Wo  = (const float*)d_in[16];
    const float* bo  = (const float*)d_in[17];
    float* out = (float*)d_out;

    float *q, *k, *v, *ki, *vi, *at;
    __nv_bfloat16 *xh, *xl, *ch, *cl, *wh, *wl, *ah, *al;
    cudaGetSymbolAddress((void**)&q,  g_q);
    cudaGetSymbolAddress((void**)&k,  g_k);
    cudaGetSymbolAddress((void**)&v,  g_v);
    cudaGetSymbolAddress((void**)&ki, g_ki);
    cudaGetSymbolAddress((void**)&vi, g_vi);
    cudaGetSymbolAddress((void**)&at, g_at);
    cudaGetSymbolAddress((void**)&xh, g_xh);
    cudaGetSymbolAddress((void**)&xl, g_xl);
    cudaGetSymbolAddress((void**)&ch, g_ch);
    cudaGetSymbolAddress((void**)&cl, g_cl);
    cudaGetSymbolAddress((void**)&wh, g_wh);
    cudaGetSymbolAddress((void**)&wl, g_wl);
    cudaGetSymbolAddress((void**)&ah, g_ah);
    cudaGetSymbolAddress((void**)&al, g_al);

    const int gemm_smem = 2 * STAGE;
    cudaFuncSetAttribute(mm_gemm, cudaFuncAttributeMaxDynamicSharedMemorySize, gemm_smem);

    // input conversions (fp32 -> hi/lo bf16)
    conv_hilo<<<4096, 256>>>(x,   xh, xl, BB * LQ * CD);
    conv_hilo<<<2048, 256>>>(ctx, ch, cl, BB * LCTX * CD);

    // weight transposes+splits: W[k][n] -> Wt[n][k] hi/lo
    const float* Ws[6] = {Wq, Wk, Wv, Wki, Wvi, Wo};
    for (int i = 0; i < 6; i++)
        wtrans<<<dim3(64, 64), dim3(32, 8)>>>(Ws[i], wh + (size_t)i * CD * CD,
                                              wl + (size_t)i * CD * CD);

    // projections via split-bf16 mma.sync GEMM
    mm_gemm<<<dim3(16, 64), 256, gemm_smem>>>(xh, xl, wh + 0 * (size_t)CD * CD,
        wl + 0 * (size_t)CD * CD, bq, q, LQ * BB, LQ * BB, LQ * BB, 0);
    rmsnorm_kernel<<<BB * LQ, 256>>>(q, gq);

    mm_gemm<<<dim3(16, 8), 256, gemm_smem>>>(ch, cl, wh + 1 * (size_t)CD * CD,
        wl + 1 * (size_t)CD * CD, bk, k, CTXT, CTXT, LCTX, IMGL);
    rmsnorm_kernel<<<BB * CTXT, 256>>>(k, gk);

    mm_gemm<<<dim3(16, 8), 256, gemm_smem>>>(ch, cl, wh + 2 * (size_t)CD * CD,
        wl + 2 * (size_t)CD * CD, bv, v, CTXT, CTXT, LCTX, IMGL);

    mm_gemm<<<dim3(16, 6), 256, gemm_smem>>>(ch, cl, wh + 3 * (size_t)CD * CD,
        wl + 3 * (size_t)CD * CD, bki, ki, IMGP, IMGL, LCTX, 0);
    rmsnorm_kernel<<<BB * IMGP, 256>>>(ki, gki);

    mm_gemm<<<dim3(16, 6), 256, gemm_smem>>>(ch, cl, wh + 4 * (size_t)CD * CD,
        wl + 4 * (size_t)CD * CD, bvi, vi, IMGP, IMGL, LCTX, 0);

    // dual-softmax attention
    const int attn_smem = (64 * 132 + 128 * 68 + 64 * 128 + 64 * 65 + 3 * 64) * 4;
    cudaFuncSetAttribute(attn_kernel, cudaFuncAttributeMaxDynamicSharedMemorySize, attn_smem);
    attn_kernel<<<dim3(64, NHEADS, BB), 256, attn_smem>>>(lens);

    // output projection
    conv_hilo<<<4096, 256>>>(at, ah, al, BB * LQ * CD);
    mm_gemm<<<dim3(16, 64), 256, gemm_smem>>>(ah, al, wh + 5 * (size_t)CD * CD,
        wl + 5 * (size_t)CD * CD, bo, out, LQ * BB, LQ * BB, LQ * BB, 0);
}